// round 5
// baseline (speedup 1.0000x reference)
#include <cuda_runtime.h>
#include <cuda_bf16.h>
#include <math.h>

// Problem constants (fixed by the reference setup_inputs)
#define E_  3
#define B_  4096
#define D_  1024
#define M_  5
#define N_  256

#define NB_DOT 512          // blocks for the big feature*gt reduction
#define NB_SIM 96           // 3 e * 32 blocks, each block = 8 warps, 1 n per warp
#define TPB 256

// total float4 pairs = 3,145,728 ; per block: 6144 contiguous float4 per array
#define CHUNK4 (3145728 / NB_DOT)   // 6144 -> 24 pairs/thread -> 4 iters of 6 pairs

// Scratch (allocation-free rule: __device__ globals)
__device__ float g_dot_partial[NB_DOT];
__device__ float g_dotmn[E_][M_][N_];   // raw dot(gt_local[m], feature_local[n])
__device__ float g_fnorm2[E_][N_];      // ||f_n||^2

static __device__ __forceinline__ float dot4(float4 a, float4 b) {
    return a.x * b.x + a.y * b.y + a.z * b.z + a.w * b.w;
}

// ---------------------------------------------------------------------------
// Kernel 1: (a) blocks [0, NB_DOT): feature*gt dot over a contiguous chunk,
//               12 front-batched LDG.128 per iteration (deep MLP);
//           (b) blocks [NB_DOT, NB_DOT+NB_SIM): sim raw dots + f-row norms.
// ---------------------------------------------------------------------------
__global__ void __launch_bounds__(TPB, 4) k_main(
    const float* __restrict__ feature,
    const float* __restrict__ gt,
    const float* __restrict__ gt_local,
    const float* __restrict__ feature_local)
{
    const int b = blockIdx.x;
    const int tid = threadIdx.x;

    if (b < NB_DOT) {
        // ---- big streaming reduction: sum(feature * gt) ----
        const float4* fa = reinterpret_cast<const float4*>(feature);
        const float4* ga = reinterpret_cast<const float4*>(gt);
        int i = b * CHUNK4 + tid;     // contiguous chunk per block
        float acc[6] = {0.f, 0.f, 0.f, 0.f, 0.f, 0.f};
        #pragma unroll 1
        for (int k = 0; k < CHUNK4 / (6 * TPB); ++k) {   // 4 iterations
            float4 x[6], y[6];
            #pragma unroll
            for (int t = 0; t < 6; ++t) x[t] = __ldcs(&fa[i + t * TPB]);
            #pragma unroll
            for (int t = 0; t < 6; ++t) y[t] = __ldcs(&ga[i + t * TPB]);
            #pragma unroll
            for (int t = 0; t < 6; ++t) acc[t] += dot4(x[t], y[t]);
            i += 6 * TPB;
        }
        float a01 = acc[0] + acc[1];
        float a23 = acc[2] + acc[3];
        float a45 = acc[4] + acc[5];
        float accs = (a01 + a23) + a45;

        // warp reduce + single-sync block reduce
        #pragma unroll
        for (int off = 16; off > 0; off >>= 1)
            accs += __shfl_down_sync(0xFFFFFFFFu, accs, off);

        __shared__ float sh[8];
        const int w = tid >> 5;
        const int lane = tid & 31;
        if (lane == 0) sh[w] = accs;
        __syncthreads();
        if (w == 0) {
            float s = (lane < 8) ? sh[lane] : 0.0f;
            #pragma unroll
            for (int off = 4; off > 0; off >>= 1)
                s += __shfl_down_sync(0xFFFFFFFFu, s, off);
            if (lane == 0) g_dot_partial[b] = s;
        }
    } else {
        // ---- sim raw dots + feature_local row norms ----
        const int sb = b - NB_DOT;          // 0..95
        const int e  = sb / 32;             // 3 extractors
        const int w  = tid >> 5;            // warp id 0..7
        const int lane = tid & 31;
        const int n  = (sb % 32) * 8 + w;   // 0..255

        const float* __restrict__ f = feature_local + ((size_t)e * N_ + n) * D_;
        const float* __restrict__ g = gt_local + (size_t)e * M_ * D_;

        float acc[M_] = {0.f, 0.f, 0.f, 0.f, 0.f};
        float fn = 0.f;
        for (int d = lane; d < D_; d += 32) {
            float fv = f[d];
            fn += fv * fv;
            #pragma unroll
            for (int m = 0; m < M_; m++)
                acc[m] += g[m * D_ + d] * fv;
        }
        #pragma unroll
        for (int off = 16; off > 0; off >>= 1) {
            fn += __shfl_down_sync(0xFFFFFFFFu, fn, off);
            #pragma unroll
            for (int m = 0; m < M_; m++)
                acc[m] += __shfl_down_sync(0xFFFFFFFFu, acc[m], off);
        }
        if (lane == 0) {
            #pragma unroll
            for (int m = 0; m < M_; m++)
                g_dotmn[e][m][n] = acc[m];
            g_fnorm2[e][n] = fn;
        }
    }
}

// ---------------------------------------------------------------------------
// Kernel 2 (fused tail): ONE block of 256 threads.
//   warps 0..2 : warp-local Sinkhorn for e = warp id (lane owns 8 columns)
//   warps 3..7 : reduce the 512 dot partials
//   then thread 0 combines everything and writes the scalar loss.
// ---------------------------------------------------------------------------
__global__ void __launch_bounds__(TPB) k_tail(
    const float* __restrict__ gt_local,
    float* __restrict__ out)
{
    const int tid = threadIdx.x;
    const int w = tid >> 5;
    const int lane = tid & 31;

    __shared__ float s_ot[E_];
    __shared__ float s_ps[5];

    if (w < E_) {
        const int e = w;
        const float* __restrict__ g = gt_local + (size_t)e * M_ * D_;

        // gt_local row norms (all lanes end with the value via xor-reduce)
        float gn[M_] = {0.f, 0.f, 0.f, 0.f, 0.f};
        for (int d = lane; d < D_; d += 32) {
            #pragma unroll
            for (int m = 0; m < M_; m++) {
                float v = g[m * D_ + d];
                gn[m] += v * v;
            }
        }
        #pragma unroll
        for (int m = 0; m < M_; m++) {
            #pragma unroll
            for (int off = 16; off > 0; off >>= 1)
                gn[m] += __shfl_xor_sync(0xFFFFFFFFu, gn[m], off);
            gn[m] = fmaxf(sqrtf(gn[m]), 1e-12f);
        }

        // lane owns columns n = j*32 + lane, j < 8
        float sim[M_][8], K[M_][8];
        #pragma unroll
        for (int j = 0; j < 8; ++j) {
            const int n = j * 32 + lane;
            const float fn = fmaxf(sqrtf(g_fnorm2[e][n]), 1e-12f);
            #pragma unroll
            for (int m = 0; m < M_; m++) {
                float s = g_dotmn[e][m][n] / (gn[m] * fn);
                sim[m][j] = s;
                K[m][j] = __expf((s - 1.0f) * 10.0f);
            }
        }

        // Sinkhorn (mirrors reference; early exit uniform across the warp)
        const float u = 1.0f / (float)M_;
        const float vv = 1.0f / (float)N_;
        float r[M_] = {1.f, 1.f, 1.f, 1.f, 1.f};
        float c[8] = {1.f, 1.f, 1.f, 1.f, 1.f, 1.f, 1.f, 1.f};
        float err = 1e9f;

        for (int it = 0; it < 100 && err >= 0.01f; ++it) {
            // Kc[m] = sum_n K[m][n] * c[n]   (lane-local 8, then xor-reduce)
            float p[M_];
            #pragma unroll
            for (int m = 0; m < M_; m++) {
                float s = 0.f;
                #pragma unroll
                for (int j = 0; j < 8; ++j) s += K[m][j] * c[j];
                #pragma unroll
                for (int off = 16; off > 0; off >>= 1)
                    s += __shfl_xor_sync(0xFFFFFFFFu, s, off);
                p[m] = s;
            }
            float errs = 0.f;
            #pragma unroll
            for (int m = 0; m < M_; m++) {
                float rn = u / p[m];          // r = u / (K @ c)
                errs += fabsf(rn - r[m]);
                r[m] = rn;
            }
            err = errs * (1.0f / (float)M_);
            // c = v / (K^T @ r)  — purely column-local, no reduction
            #pragma unroll
            for (int j = 0; j < 8; ++j) {
                float ktr = 0.f;
                #pragma unroll
                for (int m = 0; m < M_; m++) ktr += K[m][j] * r[m];
                c[j] = vv / ktr;
            }
        }

        // ot = sum_{m,n} r[m]*c[n]*K*sim
        float t = 0.f;
        #pragma unroll
        for (int j = 0; j < 8; ++j) {
            float tm = 0.f;
            #pragma unroll
            for (int m = 0; m < M_; m++) tm += r[m] * K[m][j] * sim[m][j];
            t += tm * c[j];
        }
        #pragma unroll
        for (int off = 16; off > 0; off >>= 1)
            t += __shfl_xor_sync(0xFFFFFFFFu, t, off);
        if (lane == 0) s_ot[e] = t;
    } else {
        // warps 3..7: sum the 512 dot partials (160 threads)
        const int t2 = tid - 96;     // 0..159
        float s = 0.f;
        for (int i = t2; i < NB_DOT; i += 160) s += g_dot_partial[i];
        #pragma unroll
        for (int off = 16; off > 0; off >>= 1)
            s += __shfl_xor_sync(0xFFFFFFFFu, s, off);
        if (lane == 0) s_ps[w - 3] = s;
    }
    __syncthreads();

    if (tid == 0) {
        float dot = ((s_ps[0] + s_ps[1]) + (s_ps[2] + s_ps[3])) + s_ps[4];
        float loss_global = dot / (float)(E_ * B_);
        float loss_local = (s_ot[0] + s_ot[1] + s_ot[2]) * 2.0f / (float)E_;
        out[0] = loss_global + 0.1f * loss_local;
    }
}

// ---------------------------------------------------------------------------
extern "C" void kernel_launch(void* const* d_in, const int* in_sizes, int n_in,
                              void* d_out, int out_size)
{
    const float* feature        = (const float*)d_in[0];
    const float* gt             = (const float*)d_in[1];
    const float* gt_local       = (const float*)d_in[2];
    const float* feature_local  = (const float*)d_in[3];
    float* out = (float*)d_out;

    k_main<<<NB_DOT + NB_SIM, TPB>>>(feature, gt, gt_local, feature_local);
    k_tail<<<1, TPB>>>(gt_local, out);
}

// round 6
// speedup vs baseline: 1.9376x; 1.9376x over previous
#include <cuda_runtime.h>
#include <cuda_bf16.h>
#include <math.h>

// Problem constants (fixed by the reference setup_inputs)
#define E_  3
#define B_  4096
#define D_  1024
#define M_  5
#define N_  256

#define NB_DOT 512          // blocks for the big feature*gt reduction
#define NB_SIM 96           // 3 e * 32 blocks, each block = 8 warps, 1 n per warp
#define TPB 256

// total float4 pairs = 3,145,728 ; per block: 6144 contiguous float4 per array
#define CHUNK4 (3145728 / NB_DOT)   // 6144 -> 24 pairs/thread -> 4 iters of 6 pairs

// Scratch (allocation-free rule: __device__ globals)
__device__ float g_dot_partial[NB_DOT];
__device__ float g_dotmn[E_][M_][N_];   // raw dot(gt_local[m], feature_local[n])
__device__ float g_fnorm2[E_][N_];      // ||f_n||^2
__device__ float g_ot[E_];

static __device__ __forceinline__ float dot4(float4 a, float4 b) {
    return a.x * b.x + a.y * b.y + a.z * b.z + a.w * b.w;
}

// ---------------------------------------------------------------------------
// Kernel 1: (a) blocks [0, NB_DOT): feature*gt dot over a contiguous chunk,
//               12 front-batched LDG.128 per iteration (deep MLP);
//           (b) blocks [NB_DOT, NB_DOT+NB_SIM): sim raw dots + f-row norms.
// ---------------------------------------------------------------------------
__global__ void __launch_bounds__(TPB, 4) k_main(
    const float* __restrict__ feature,
    const float* __restrict__ gt,
    const float* __restrict__ gt_local,
    const float* __restrict__ feature_local)
{
    const int b = blockIdx.x;
    const int tid = threadIdx.x;

    if (b < NB_DOT) {
        // ---- big streaming reduction: sum(feature * gt) ----
        const float4* fa = reinterpret_cast<const float4*>(feature);
        const float4* ga = reinterpret_cast<const float4*>(gt);
        int i = b * CHUNK4 + tid;     // contiguous chunk per block
        float acc[6] = {0.f, 0.f, 0.f, 0.f, 0.f, 0.f};
        #pragma unroll 1
        for (int k = 0; k < CHUNK4 / (6 * TPB); ++k) {   // 4 iterations
            float4 x[6], y[6];
            #pragma unroll
            for (int t = 0; t < 6; ++t) x[t] = __ldcs(&fa[i + t * TPB]);
            #pragma unroll
            for (int t = 0; t < 6; ++t) y[t] = __ldcs(&ga[i + t * TPB]);
            #pragma unroll
            for (int t = 0; t < 6; ++t) acc[t] += dot4(x[t], y[t]);
            i += 6 * TPB;
        }
        float a01 = acc[0] + acc[1];
        float a23 = acc[2] + acc[3];
        float a45 = acc[4] + acc[5];
        float accs = (a01 + a23) + a45;

        // warp reduce + single-sync block reduce
        #pragma unroll
        for (int off = 16; off > 0; off >>= 1)
            accs += __shfl_down_sync(0xFFFFFFFFu, accs, off);

        __shared__ float sh[8];
        const int w = tid >> 5;
        const int lane = tid & 31;
        if (lane == 0) sh[w] = accs;
        __syncthreads();
        if (w == 0) {
            float s = (lane < 8) ? sh[lane] : 0.0f;
            #pragma unroll
            for (int off = 4; off > 0; off >>= 1)
                s += __shfl_down_sync(0xFFFFFFFFu, s, off);
            if (lane == 0) g_dot_partial[b] = s;
        }
    } else {
        // ---- sim raw dots + feature_local row norms ----
        const int sb = b - NB_DOT;          // 0..95
        const int e  = sb / 32;             // 3 extractors
        const int w  = tid >> 5;            // warp id 0..7
        const int lane = tid & 31;
        const int n  = (sb % 32) * 8 + w;   // 0..255

        const float* __restrict__ f = feature_local + ((size_t)e * N_ + n) * D_;
        const float* __restrict__ g = gt_local + (size_t)e * M_ * D_;

        float acc[M_] = {0.f, 0.f, 0.f, 0.f, 0.f};
        float fn = 0.f;
        for (int d = lane; d < D_; d += 32) {
            float fv = f[d];
            fn += fv * fv;
            #pragma unroll
            for (int m = 0; m < M_; m++)
                acc[m] += g[m * D_ + d] * fv;
        }
        #pragma unroll
        for (int off = 16; off > 0; off >>= 1) {
            fn += __shfl_down_sync(0xFFFFFFFFu, fn, off);
            #pragma unroll
            for (int m = 0; m < M_; m++)
                acc[m] += __shfl_down_sync(0xFFFFFFFFu, acc[m], off);
        }
        if (lane == 0) {
            #pragma unroll
            for (int m = 0; m < M_; m++)
                g_dotmn[e][m][n] = acc[m];
            g_fnorm2[e][n] = fn;
        }
    }
}

// ---------------------------------------------------------------------------
// Kernel 2: per-extractor Sinkhorn (one 256-thread block per e).
// Thread t owns column n = t of the 5 x 256 sim/K matrices (in registers).
// (Proven-fast R2 version.)
// ---------------------------------------------------------------------------
__global__ void __launch_bounds__(TPB) k_sinkhorn(
    const float* __restrict__ gt_local)
{
    const int e = blockIdx.x;
    const int tid = threadIdx.x;         // == n
    const int w = tid >> 5;
    const int lane = tid & 31;

    __shared__ float sh_gn[M_];          // ||g_m||
    __shared__ float sred[8 * M_];       // per-warp partials for K@c
    __shared__ float sh_r[M_];           // row scaling vector
    __shared__ float sh_scalar[8];       // final reduction

    // gt_local row norms: warps 0..4, one row each
    if (w < M_) {
        const float* g = gt_local + ((size_t)e * M_ + w) * D_;
        float s = 0.f;
        for (int d = lane; d < D_; d += 32) {
            float v = g[d];
            s += v * v;
        }
        #pragma unroll
        for (int off = 16; off > 0; off >>= 1)
            s += __shfl_down_sync(0xFFFFFFFFu, s, off);
        if (lane == 0) sh_gn[w] = sqrtf(s);
    }
    __syncthreads();

    // Build sim[m][n] and K[m][n] in registers
    const float fn = fmaxf(sqrtf(g_fnorm2[e][tid]), 1e-12f);
    float simv[M_], Kv[M_];
    #pragma unroll
    for (int m = 0; m < M_; m++) {
        const float gn = fmaxf(sh_gn[m], 1e-12f);
        simv[m] = g_dotmn[e][m][tid] / (gn * fn);
        Kv[m] = __expf((simv[m] - 1.0f) * 10.0f);   // exp(-(1-sim)/0.1)
    }

    // Sinkhorn loop (mirrors the reference exactly)
    const float u = 1.0f / (float)M_;
    const float vv = 1.0f / (float)N_;
    float c = 1.0f;
    float r[M_] = {1.f, 1.f, 1.f, 1.f, 1.f};
    float err = 1e9f;

    for (int it = 0; it < 100 && err >= 0.01f; ++it) {
        // Kc[m] = sum_n K[m][n] * c[n]
        float p[M_];
        #pragma unroll
        for (int m = 0; m < M_; m++) p[m] = Kv[m] * c;
        #pragma unroll
        for (int off = 16; off > 0; off >>= 1) {
            #pragma unroll
            for (int m = 0; m < M_; m++)
                p[m] += __shfl_down_sync(0xFFFFFFFFu, p[m], off);
        }
        if (lane == 0) {
            #pragma unroll
            for (int m = 0; m < M_; m++) sred[w * M_ + m] = p[m];
        }
        __syncthreads();
        if (tid < M_) {
            float s = 0.f;
            #pragma unroll
            for (int ww = 0; ww < 8; ww++) s += sred[ww * M_ + tid];
            sh_r[tid] = u / s;           // r = u / (K @ c)
        }
        __syncthreads();
        // all threads: identical update of r, err, c  (uniform branch)
        float errs = 0.f;
        #pragma unroll
        for (int m = 0; m < M_; m++) {
            float rn = sh_r[m];
            errs += fabsf(rn - r[m]);
            r[m] = rn;
        }
        err = errs * (1.0f / (float)M_);
        float ktr = 0.f;
        #pragma unroll
        for (int m = 0; m < M_; m++) ktr += Kv[m] * r[m];
        c = vv / ktr;                    // c = v / (K^T @ r)
    }

    // ot = sum_{m,n} r[m]*c[n]*K[m][n]*sim[m][n]
    float t = 0.f;
    #pragma unroll
    for (int m = 0; m < M_; m++) t += r[m] * Kv[m] * simv[m];
    t *= c;
    #pragma unroll
    for (int off = 16; off > 0; off >>= 1)
        t += __shfl_down_sync(0xFFFFFFFFu, t, off);
    if (lane == 0) sh_scalar[w] = t;
    __syncthreads();
    if (tid == 0) {
        float s = 0.f;
        #pragma unroll
        for (int ww = 0; ww < 8; ww++) s += sh_scalar[ww];
        g_ot[e] = s;
    }
}

// ---------------------------------------------------------------------------
// Kernel 3: finalize — deterministic sum of partials + scalar combine
// ---------------------------------------------------------------------------
__global__ void __launch_bounds__(TPB) k_final(float* __restrict__ out)
{
    const int tid = threadIdx.x;
    __shared__ float sh[TPB];
    float s = 0.f;
    for (int i = tid; i < NB_DOT; i += TPB) s += g_dot_partial[i];
    sh[tid] = s;
    __syncthreads();
    #pragma unroll
    for (int st = TPB / 2; st > 0; st >>= 1) {
        if (tid < st) sh[tid] += sh[tid + st];
        __syncthreads();
    }
    if (tid == 0) {
        float loss_global = sh[0] / (float)(E_ * B_);
        float loss_local = (g_ot[0] + g_ot[1] + g_ot[2]) * 2.0f / (float)E_;
        out[0] = loss_global + 0.1f * loss_local;
    }
}

// ---------------------------------------------------------------------------
extern "C" void kernel_launch(void* const* d_in, const int* in_sizes, int n_in,
                              void* d_out, int out_size)
{
    const float* feature        = (const float*)d_in[0];
    const float* gt             = (const float*)d_in[1];
    const float* gt_local       = (const float*)d_in[2];
    const float* feature_local  = (const float*)d_in[3];
    float* out = (float*)d_out;

    k_main<<<NB_DOT + NB_SIM, TPB>>>(feature, gt, gt_local, feature_local);
    k_sinkhorn<<<E_, TPB>>>(gt_local);
    k_final<<<1, TPB>>>(out);
}